// round 2
// baseline (speedup 1.0000x reference)
#include <cuda_runtime.h>
#include <cstdint>

// ---------------- problem constants (shapes fixed by the dataset) -----------
#define NF        128          // node features == H*D
#define NOUT      256          // 128 (src proj) + 128 (dst proj)
#define NC        12           // 11 spline columns + 1 base(silu) column
#define NT        64           // nodes per projection block
#define MAXN      50000
#define MAXE      800000
#define WCHUNK    20           // padded smem stride per 16-float output chunk
#define WROW      (16*WCHUNK)  // 320 floats per c-row in smem

// ---------------- scratch (no cudaMalloc allowed) ----------------------------
__device__ __align__(16) float g_Wt[NF * NC * NOUT];     // [f][c][o]  (~1.57 MB)
__device__ __align__(16) float g_sp[(size_t)MAXN * NF];  // src projection
__device__ __align__(16) float g_dp[(size_t)MAXN * NF];  // dst projection
__device__ __align__(16) float g_attn[(size_t)MAXE * 4]; // raw attention logits
__device__ __align__(16) float g_exp[(size_t)MAXE * 4];  // exp(attn - max)
__device__ __align__(16) float g_denom[(size_t)MAXN * 4];// softmax denominators
__device__ unsigned int g_max_u;                         // global max (ordered enc)
__device__ int g_is64;                                   // edge_index dtype flag

// ordered-uint encoding for float atomicMax (handles negatives)
__device__ __forceinline__ unsigned int enc_f(float f) {
    unsigned int u = __float_as_uint(f);
    return (u & 0x80000000u) ? ~u : (u | 0x80000000u);
}
__device__ __forceinline__ float dec_f(unsigned int e) {
    unsigned int u = (e & 0x80000000u) ? (e ^ 0x80000000u) : ~e;
    return __uint_as_float(u);
}

// fetch edge index element `pos` honoring detected dtype
__device__ __forceinline__ long long get_idx(const void* ei, long long pos, int is64) {
    if (is64) return ((const long long*)ei)[pos];
    return (long long)((const int*)ei)[pos];
}

// ---------------- kernel 0: detect edge_index dtype ---------------------------
__global__ void detect_kernel(const int* __restrict__ ei_words, long long E) {
    if (blockIdx.x == 0 && threadIdx.x == 0) {
        int n = (int)(E < 512 ? E : 512);
        int nonzero = 0;
        for (int i = 0; i < n; i++) nonzero += (ei_words[2 * i + 1] != 0);
        g_is64 = (nonzero == 0) ? 1 : 0;
    }
}

// ---------------- kernel Z: zero output / denom / max ------------------------
__global__ void zero_kernel(float* outf, long long nout, long long ndenom) {
    long long i = (long long)blockIdx.x * blockDim.x + threadIdx.x;
    if (i < nout)  outf[i] = 0.0f;
    if (i < ndenom) g_denom[i] = 0.0f;
    if (i == 0)     g_max_u = 0u;
}

// ---------------- kernel A: transpose / fuse weights -------------------------
// g_Wt[f][c][o]: c<11 -> spline weight [o,f,c]; c==11 -> base weight [o,f].
// o<128 uses the src projection weights, o>=128 the dst ones.
__global__ void prep_wt_kernel(const float* __restrict__ bw_s, const float* __restrict__ sw_s,
                               const float* __restrict__ bw_d, const float* __restrict__ sw_d) {
    int idx = blockIdx.x * blockDim.x + threadIdx.x;  // f*3072 + c*256 + o
    if (idx >= NF * NC * NOUT) return;
    int o = idx & 255;
    int c = (idx >> 8) % NC;
    int f = idx / (NC * NOUT);
    float v;
    if (o < 128) v = (c < 11) ? sw_s[((size_t)o * NF + f) * 11 + c] : bw_s[(size_t)o * NF + f];
    else {
        int oo = o - 128;
        v = (c < 11) ? sw_d[((size_t)oo * NF + f) * 11 + c] : bw_d[(size_t)oo * NF + f];
    }
    g_Wt[idx] = v;
}

// ---------------- kernel B: KAN projections (both at once) -------------------
// Block: 64 nodes x 256 outputs. 256 threads: tx=out-group(16 outs), ty=node row.
// Each thread: 4 nodes x 16 outputs, accumulated in packed f32x2 registers.
__global__ __launch_bounds__(256, 2) void proj_kernel(const float* __restrict__ x, int N) {
    __shared__ __align__(16) float ws[NC * WROW];   // weight slice for current f
    __shared__ __align__(16) float acts[NT * 13];   // activation vec per node (pad 13)

    const int tid = threadIdx.x;
    const int tx = tid & 15;
    const int ty = tid >> 4;
    const int node0 = blockIdx.x * NT;

    unsigned long long acc[4][8];
#pragma unroll
    for (int n = 0; n < 4; n++)
#pragma unroll
        for (int j = 0; j < 8; j++) acc[n][j] = 0ull;

    for (int f = 0; f < NF; f++) {
        __syncthreads();  // previous iteration's consumers done
        if (tid < NT) {
            // activation vector for node `node0+tid` at feature f
            float* ap = &acts[tid * 13];
#pragma unroll
            for (int c = 0; c < 12; c++) ap[c] = 0.0f;
            int node = node0 + tid;
            if (node < N) {
                float xv = x[(size_t)node * NF + f];
                ap[11] = xv / (1.0f + __expf(-xv));           // silu
                if (xv >= -1.75f && xv < 1.75f) {
                    float t = (xv + 1.75f) * 4.0f;
                    int m = (int)t; if (m > 13) m = 13;
                    float u = t - (float)m;
                    float u1 = 1.0f - u;
                    float uu = u * u, uuu = uu * u;
                    float w0 = u1 * u1 * u1 * (1.0f / 6.0f);
                    float w1 = (3.0f * uuu - 6.0f * uu + 4.0f) * (1.0f / 6.0f);
                    float w2 = (-3.0f * uuu + 3.0f * uu + 3.0f * u + 1.0f) * (1.0f / 6.0f);
                    float w3 = uuu * (1.0f / 6.0f);
                    int c0 = m - 3;
                    if (c0 >= 0 && c0 <= 10)         ap[c0]     = w0;
                    if (c0 + 1 >= 0 && c0 + 1 <= 10) ap[c0 + 1] = w1;
                    if (c0 + 2 >= 0 && c0 + 2 <= 10) ap[c0 + 2] = w2;
                    if (c0 + 3 <= 10)                ap[c0 + 3] = w3;
                }
            }
        } else {
            // load W slice for this f: 12*256 floats -> swizzled chunks of 16 (+4 pad)
            int t = tid - 64;  // 0..191
            const float4* wg = (const float4*)(g_Wt + (size_t)f * (NC * NOUT));
            float4* ws4 = (float4*)ws;
#pragma unroll
            for (int i = 0; i < 4; i++) {
                int q = t + i * 192;        // logical float4 index: c*64 + txw*4 + s
                int c = q >> 6;
                int r = q & 63;
                int txw = r >> 2, s = r & 3;
                ws4[c * (WROW / 4) + txw * (WCHUNK / 4) + s] = wg[q];
            }
        }
        __syncthreads();

#pragma unroll
        for (int c = 0; c < 12; c++) {
            const double2* wp = (const double2*)&ws[c * WROW + tx * WCHUNK];
            double2 q0 = wp[0], q1 = wp[1], q2 = wp[2], q3 = wp[3];
            unsigned long long wv[8];
            wv[0] = __double_as_longlong(q0.x); wv[1] = __double_as_longlong(q0.y);
            wv[2] = __double_as_longlong(q1.x); wv[3] = __double_as_longlong(q1.y);
            wv[4] = __double_as_longlong(q2.x); wv[5] = __double_as_longlong(q2.y);
            wv[6] = __double_as_longlong(q3.x); wv[7] = __double_as_longlong(q3.y);
#pragma unroll
            for (int n = 0; n < 4; n++) {
                float av = acts[(ty + n * 16) * 13 + c];
                unsigned long long avp;
                asm("mov.b64 %0, {%1, %1};" : "=l"(avp) : "r"(__float_as_uint(av)));
#pragma unroll
                for (int j = 0; j < 8; j++) {
                    asm("fma.rn.f32x2 %0, %1, %2, %0;"
                        : "+l"(acc[n][j]) : "l"(wv[j]), "l"(avp));
                }
            }
        }
    }

    // write out: 16 contiguous outputs per (thread,node)
#pragma unroll
    for (int n = 0; n < 4; n++) {
        int node = node0 + ty + n * 16;
        if (node >= N) continue;
        float o16[16];
#pragma unroll
        for (int j = 0; j < 8; j++) {
            unsigned long long v = acc[n][j];
            o16[2 * j]     = __uint_as_float((unsigned int)v);
            o16[2 * j + 1] = __uint_as_float((unsigned int)(v >> 32));
        }
        float* bp = (tx < 8) ? (g_sp + (size_t)node * NF + tx * 16)
                             : (g_dp + (size_t)node * NF + (tx - 8) * 16);
#pragma unroll
        for (int j = 0; j < 4; j++) {
            float4 v = make_float4(o16[4 * j], o16[4 * j + 1], o16[4 * j + 2], o16[4 * j + 3]);
            ((float4*)bp)[j] = v;
        }
    }
}

// ---------------- kernel C: edge attention logits + global max ---------------
__global__ void edge_attn_kernel(const void* __restrict__ ei, long long E,
                                 const float* __restrict__ da) {
    __shared__ __align__(16) float da_s[128];
    if (threadIdx.x < 128) da_s[threadIdx.x] = da[threadIdx.x];
    __syncthreads();

    const int is64 = g_is64;
    long long idx = (long long)blockIdx.x * blockDim.x + threadIdx.x;
    bool valid = idx < E * 4;
    float acc = 0.0f;
    if (valid) {
        long long e = idx >> 2;
        int h = (int)(idx & 3);
        long long s = get_idx(ei, e, is64);
        long long d = get_idx(ei, E + e, is64);
        const float4* sp4 = (const float4*)(g_sp + s * NF + h * 32);
        const float4* dp4 = (const float4*)(g_dp + d * NF + h * 32);
        const float4* wa4 = (const float4*)(da_s + h * 32);
#pragma unroll
        for (int g = 0; g < 8; g++) {
            float4 a = sp4[g], b = dp4[g], w = wa4[g];
            float v;
            v = a.x + b.x; v = v >= 0.0f ? v : 0.2f * v; acc += w.x * v;
            v = a.y + b.y; v = v >= 0.0f ? v : 0.2f * v; acc += w.y * v;
            v = a.z + b.z; v = v >= 0.0f ? v : 0.2f * v; acc += w.z * v;
            v = a.w + b.w; v = v >= 0.0f ? v : 0.2f * v; acc += w.w * v;
        }
        g_attn[idx] = acc;
    }
    float m = valid ? acc : -3.4e38f;
#pragma unroll
    for (int o = 16; o; o >>= 1) m = fmaxf(m, __shfl_xor_sync(0xffffffffu, m, o));
    if ((threadIdx.x & 31) == 0) atomicMax(&g_max_u, enc_f(m));
}

// ---------------- kernel D: exp + softmax denominators -----------------------
__global__ void edge_exp_kernel(const void* __restrict__ ei, long long E) {
    const int is64 = g_is64;
    long long idx = (long long)blockIdx.x * blockDim.x + threadIdx.x;
    if (idx >= E * 4) return;
    float gmax = dec_f(g_max_u);
    long long e = idx >> 2;
    int h = (int)(idx & 3);
    float ea = expf(g_attn[idx] - gmax);
    g_exp[idx] = ea;
    long long d = get_idx(ei, E + e, is64);
    atomicAdd(&g_denom[d * 4 + h], ea);
}

// ---------------- kernel E: weighted aggregation (warp per edge) -------------
__global__ void edge_agg_kernel(const void* __restrict__ ei, long long E,
                                float* __restrict__ outf) {
    const int is64 = g_is64;
    int lane = threadIdx.x & 31;
    long long e = (long long)blockIdx.x * 8 + (threadIdx.x >> 5);
    if (e >= E) return;
    long long s = get_idx(ei, e, is64);
    long long d = get_idx(ei, E + e, is64);
    float al = 0.0f;
    if (lane < 4) al = g_exp[e * 4 + lane] / (g_denom[d * 4 + lane] + 1e-16f);
    float a0 = __shfl_sync(0xffffffffu, al, 0);
    float a1 = __shfl_sync(0xffffffffu, al, 1);
    float a2 = __shfl_sync(0xffffffffu, al, 2);
    float a3 = __shfl_sync(0xffffffffu, al, 3);
    const float* sp = g_sp + s * NF;
    float* op = outf + d * NF;
    atomicAdd(&op[lane],      sp[lane]      * a0);
    atomicAdd(&op[32 + lane], sp[32 + lane] * a1);
    atomicAdd(&op[64 + lane], sp[64 + lane] * a2);
    atomicAdd(&op[96 + lane], sp[96 + lane] * a3);
}

// ---------------- kernel G: residual + bias + PReLU ---------------------------
__global__ void finalize_kernel(const float* __restrict__ x, const float* __restrict__ bias,
                                const float* __restrict__ pa, float* __restrict__ outf,
                                long long total) {
    long long i = (long long)blockIdx.x * blockDim.x + threadIdx.x;
    if (i >= total) return;
    float v = outf[i] + x[i] + bias[i & 127];
    float a = pa[0];
    outf[i] = v >= 0.0f ? v : a * v;
}

// ---------------- launch -------------------------------------------------------
extern "C" void kernel_launch(void* const* d_in, const int* in_sizes, int n_in,
                              void* d_out, int out_size) {
    const float* x    = (const float*)d_in[0];
    const void*  ei   = d_in[1];
    const float* bw_s = (const float*)d_in[2];
    const float* sw_s = (const float*)d_in[3];
    const float* bw_d = (const float*)d_in[4];
    const float* sw_d = (const float*)d_in[5];
    const float* da   = (const float*)d_in[6];
    const float* bias = (const float*)d_in[7];
    const float* pa   = (const float*)d_in[8];
    float* outf = (float*)d_out;

    int       N = in_sizes[0] / NF;
    long long E = (long long)in_sizes[1] / 2;
    long long total = (long long)N * NF;

    detect_kernel<<<1, 32>>>((const int*)ei, E);
    zero_kernel<<<(int)((total + 255) / 256), 256>>>(outf, total, (long long)N * 4);
    prep_wt_kernel<<<(NF * NC * NOUT + 255) / 256, 256>>>(bw_s, sw_s, bw_d, sw_d);
    proj_kernel<<<(N + NT - 1) / NT, 256>>>(x, N);
    edge_attn_kernel<<<(int)((E * 4 + 255) / 256), 256>>>(ei, E, da);
    edge_exp_kernel<<<(int)((E * 4 + 255) / 256), 256>>>(ei, E);
    edge_agg_kernel<<<(int)((E + 7) / 8), 256>>>(ei, E, outf);
    finalize_kernel<<<(int)((total + 255) / 256), 256>>>(x, bias, pa, outf, total);
}

// round 4
// speedup vs baseline: 1.4935x; 1.4935x over previous
#include <cuda_runtime.h>
#include <cuda_bf16.h>
#include <cstdint>

// ---------------- problem constants -----------------------------------------
#define NF     128           // node features == H*D
#define MAXN   50000
#define MAXE   800000
#define TILE_M 128           // nodes per CTA
#define NIT    32            // K iterations (128 features / 4 per iter)
#define KC     48            // K per iteration (4 features x 12 cols)
#define BPITCH 56            // bf16 col pitch (112 bytes) for A and B tiles
#define BTILE_BYTES (2 * 256 * BPITCH * 2)   // hi+lo, 256 rows, bf16 = 57344

// smem layout (bytes)
#define XS_BYTES (128 * 132 * 4)             // 67584: x tile fp32, pitch 132
#define SA_OFF   XS_BYTES                    // A hi (14336), A lo at +14336
#define SB_OFF   (SA_OFF + 28672)            // two B buffers of 57344 each
#define SMEM_BYTES (SB_OFF + 2 * BTILE_BYTES)  // 210944

// ---------------- scratch (no cudaMalloc allowed) ----------------------------
__device__ __align__(16) __nv_bfloat16 g_Bt[NIT * 2 * 256 * BPITCH]; // pre-split W tiles
__device__ __align__(16) float g_sp[(size_t)MAXN * NF];   // src projection
__device__ __align__(16) float g_dp[(size_t)MAXN * NF];   // dst projection
__device__ __align__(16) float g_exp[(size_t)MAXE * 4];   // exp(attn)
__device__ __align__(16) float g_denom[(size_t)MAXN * 4]; // softmax denominators
__device__ int g_is64;                                    // edge_index dtype flag

// ---------------- helpers -----------------------------------------------------
__device__ __forceinline__ uint32_t smem_u32(const void* p) {
    uint32_t a;
    asm("{ .reg .u64 t; cvta.to.shared.u64 t, %1; cvt.u32.u64 %0, t; }" : "=r"(a) : "l"(p));
    return a;
}
__device__ __forceinline__ void ldsm_x4(uint32_t addr, uint32_t* r) {
    asm volatile("ldmatrix.sync.aligned.m8n8.x4.shared.b16 {%0,%1,%2,%3}, [%4];"
                 : "=r"(r[0]), "=r"(r[1]), "=r"(r[2]), "=r"(r[3]) : "r"(addr));
}
__device__ __forceinline__ void mma_bf16(float* c, const uint32_t* a, uint32_t b0, uint32_t b1) {
    asm volatile("mma.sync.aligned.m16n8k16.row.col.f32.bf16.bf16.f32 "
                 "{%0,%1,%2,%3}, {%4,%5,%6,%7}, {%8,%9}, {%0,%1,%2,%3};"
                 : "+f"(c[0]), "+f"(c[1]), "+f"(c[2]), "+f"(c[3])
                 : "r"(a[0]), "r"(a[1]), "r"(a[2]), "r"(a[3]), "r"(b0), "r"(b1));
}
__device__ __forceinline__ long long get_idx(const void* ei, long long pos, int is64) {
    if (is64) return ((const long long*)ei)[pos];
    return (long long)((const int*)ei)[pos];
}

// ---------------- kernel 0: detect edge_index dtype ---------------------------
__global__ void detect_kernel(const int* __restrict__ ei_words, long long E) {
    if (blockIdx.x == 0 && threadIdx.x == 0) {
        int n = (int)(E < 512 ? E : 512);
        int nonzero = 0;
        for (int i = 0; i < n; i++) nonzero += (ei_words[2 * i + 1] != 0);
        g_is64 = (nonzero == 0) ? 1 : 0;
    }
}

// ---------------- kernel Z: zero output / denom -------------------------------
__global__ void zero_kernel(float* outf, long long nout, long long ndenom) {
    long long i = (long long)blockIdx.x * blockDim.x + threadIdx.x;
    if (i < nout)  outf[i] = 0.0f;
    if (i < ndenom) g_denom[i] = 0.0f;
}

// ---------------- kernel A: build pre-split bf16 weight tiles -----------------
// g_Bt layout == smem B-buffer image: per iter: [hi: 256 x 56][lo: 256 x 56].
// col j<48: f = it*4 + j/12, c = j%12 (c<11 spline, c==11 base). rows: o<128 src.
__global__ void prep_wt_kernel(const float* __restrict__ bw_s, const float* __restrict__ sw_s,
                               const float* __restrict__ bw_d, const float* __restrict__ sw_d) {
    int idx = blockIdx.x * blockDim.x + threadIdx.x;
    if (idx >= NIT * 2 * 256 * BPITCH) return;
    int col  = idx % BPITCH;
    int n    = (idx / BPITCH) & 255;
    int half = (idx / (BPITCH * 256)) & 1;
    int it   = idx / (BPITCH * 256 * 2);
    float v = 0.0f;
    if (col < 48) {
        int f = it * 4 + col / 12;
        int c = col % 12;
        if (n < 128) v = (c < 11) ? sw_s[((size_t)n * NF + f) * 11 + c] : bw_s[(size_t)n * NF + f];
        else {
            int oo = n - 128;
            v = (c < 11) ? sw_d[((size_t)oo * NF + f) * 11 + c] : bw_d[(size_t)oo * NF + f];
        }
    }
    __nv_bfloat16 h = __float2bfloat16_rn(v);
    g_Bt[idx] = (half == 0) ? h : __float2bfloat16_rn(v - __bfloat162float(h));
}

// ---------------- kernel B: KAN projections via bf16 mma.sync (3-split) -------
__global__ __launch_bounds__(256, 1) void proj_gemm_kernel(const float* __restrict__ x, int N) {
    extern __shared__ __align__(16) char smem[];
    const int tid  = threadIdx.x;
    const int lane = tid & 31;
    const int wid  = tid >> 5;
    const int wm   = wid >> 2;      // warp M index (0..1) -> 64 rows
    const int wn   = wid & 3;       // warp N index (0..3) -> 64 cols
    const int node0 = blockIdx.x * TILE_M;

    float* xs = (float*)smem;
    const uint32_t sb = smem_u32(smem);
    const uint32_t sA = sb + SA_OFF;
    const uint32_t sB = sb + SB_OFF;

    // stage x tile (fp32, pitch 132 floats)
    for (int i = tid; i < 128 * 32; i += 256) {
        int r = i >> 5, c4 = i & 31;
        float4 v = make_float4(0.f, 0.f, 0.f, 0.f);
        if (node0 + r < N) v = ((const float4*)(x + (size_t)(node0 + r) * NF))[c4];
        *(float4*)(xs + r * 132 + c4 * 4) = v;
    }
    __syncthreads();

    // prefetch B tile 0
    {
        unsigned long long src = (unsigned long long)__cvta_generic_to_global(g_Bt);
        for (int c = tid; c < BTILE_BYTES / 16; c += 256)
            asm volatile("cp.async.cg.shared.global [%0], [%1], 16;"
                         :: "r"(sB + c * 16), "l"(src + (unsigned long long)c * 16));
        asm volatile("cp.async.commit_group;" ::: "memory");
    }

    float acc[32][4];
#pragma unroll
    for (int i = 0; i < 32; i++)
#pragma unroll
        for (int j = 0; j < 4; j++) acc[i][j] = 0.0f;

    // per-thread ldmatrix base addresses
    const uint32_t aAddr = sA + (wm * 64 + (lane & 15)) * 112 + (lane >> 4) * 16;
    const uint32_t bOff  = (wn * 64 + (lane & 7) + ((lane >> 4) << 3)) * 112 + ((lane >> 3) & 1) * 16;

    for (int it = 0; it < NIT; it++) {
        // ---- build activations: 128 nodes x 4 features -> A hi/lo (bf16) ----
#pragma unroll
        for (int k2 = 0; k2 < 2; k2++) {
            int t = tid + k2 * 256;
            int r = t & 127, q = t >> 7;
            float xv = xs[r * 132 + it * 4 + q];
            float ap[12];
#pragma unroll
            for (int c = 0; c < 12; c++) ap[c] = 0.0f;
            ap[11] = xv / (1.0f + __expf(-xv));              // silu
            if (xv >= -1.75f && xv < 1.75f) {
                float tt = (xv + 1.75f) * 4.0f;
                int m = (int)tt; if (m > 13) m = 13;
                float u = tt - (float)m;
                float u1 = 1.0f - u;
                float uu = u * u, uuu = uu * u;
                float w0 = u1 * u1 * u1 * (1.0f / 6.0f);
                float w1 = (3.0f * uuu - 6.0f * uu + 4.0f) * (1.0f / 6.0f);
                float w2 = (-3.0f * uuu + 3.0f * uu + 3.0f * u + 1.0f) * (1.0f / 6.0f);
                float w3 = uuu * (1.0f / 6.0f);
                int c0 = m - 3;
                if (c0 >= 0 && c0 <= 10)         ap[c0]     = w0;
                if (c0 + 1 >= 0 && c0 + 1 <= 10) ap[c0 + 1] = w1;
                if (c0 + 2 >= 0 && c0 + 2 <= 10) ap[c0 + 2] = w2;
                if (c0 + 3 <= 10)                ap[c0 + 3] = w3;
            }
            uint32_t wbase = sA + r * 112 + q * 24;
#pragma unroll
            for (int j = 0; j < 6; j++) {
                float v0 = ap[2 * j], v1 = ap[2 * j + 1];
                __nv_bfloat162 hp = __floats2bfloat162_rn(v0, v1);
                float2 hf = __bfloat1622float2(hp);
                __nv_bfloat162 lp = __floats2bfloat162_rn(v0 - hf.x, v1 - hf.y);
                asm volatile("st.shared.b32 [%0], %1;" :: "r"(wbase + j * 4), "r"(*(uint32_t*)&hp));
                asm volatile("st.shared.b32 [%0], %1;" :: "r"(wbase + 14336 + j * 4), "r"(*(uint32_t*)&lp));
            }
        }
        asm volatile("cp.async.wait_group 0;" ::: "memory");
        __syncthreads();

        // prefetch next B tile into the other buffer
        if (it + 1 < NIT) {
            uint32_t bufNxt = sB + ((it + 1) & 1) * BTILE_BYTES;
            unsigned long long src = (unsigned long long)__cvta_generic_to_global(g_Bt)
                                   + (unsigned long long)(it + 1) * BTILE_BYTES;
            for (int c = tid; c < BTILE_BYTES / 16; c += 256)
                asm volatile("cp.async.cg.shared.global [%0], [%1], 16;"
                             :: "r"(bufNxt + c * 16), "l"(src + (unsigned long long)c * 16));
            asm volatile("cp.async.commit_group;" ::: "memory");
        }

        // ---- compute: 3 K16 steps x 3 products ----
        const uint32_t bBase = sB + (it & 1) * BTILE_BYTES + bOff;
#pragma unroll 1
        for (int ks = 0; ks < 3; ks++) {
            uint32_t ah[4][4], al[4][4], bb[4][4];
#pragma unroll
            for (int mi = 0; mi < 4; mi++) {
                ldsm_x4(aAddr + mi * 1792 + ks * 32, ah[mi]);
                ldsm_x4(aAddr + 14336 + mi * 1792 + ks * 32, al[mi]);
            }
#pragma unroll
            for (int nf2 = 0; nf2 < 4; nf2++) ldsm_x4(bBase + nf2 * 1792 + ks * 32, bb[nf2]);
#pragma unroll
            for (int mi = 0; mi < 4; mi++)
#pragma unroll
                for (int nf = 0; nf < 8; nf++) {
                    uint32_t b0 = bb[nf >> 1][(nf & 1) * 2], b1 = bb[nf >> 1][(nf & 1) * 2 + 1];
                    mma_bf16(acc[mi * 8 + nf], ah[mi], b0, b1);
                    mma_bf16(acc[mi * 8 + nf], al[mi], b0, b1);
                }
#pragma unroll
            for (int nf2 = 0; nf2 < 4; nf2++) ldsm_x4(bBase + 28672 + nf2 * 1792 + ks * 32, bb[nf2]);
#pragma unroll
            for (int mi = 0; mi < 4; mi++)
#pragma unroll
                for (int nf = 0; nf < 8; nf++)
                    mma_bf16(acc[mi * 8 + nf], ah[mi],
                             bb[nf >> 1][(nf & 1) * 2], bb[nf >> 1][(nf & 1) * 2 + 1]);
        }
        __syncthreads();
    }

    // ---- epilogue: write fragments (warp wn<2 -> g_sp, wn>=2 -> g_dp) ----
    float* dstbase = (wn < 2) ? g_sp : g_dp;
    const int colbase = (wn & 1) * 64 + (lane & 3) * 2;
#pragma unroll
    for (int mi = 0; mi < 4; mi++) {
        int node = node0 + wm * 64 + mi * 16 + (lane >> 2);
#pragma unroll
        for (int nf = 0; nf < 8; nf++) {
            int col = colbase + nf * 8;
            if (node < N)
                *(float2*)(dstbase + (size_t)node * NF + col)
                    = make_float2(acc[mi * 8 + nf][0], acc[mi * 8 + nf][1]);
            if (node + 8 < N)
                *(float2*)(dstbase + (size_t)(node + 8) * NF + col)
                    = make_float2(acc[mi * 8 + nf][2], acc[mi * 8 + nf][3]);
        }
    }
}

// ---------------- kernel C: edge attention + exp + denom (fused) --------------
__global__ void edge_attn_kernel(const void* __restrict__ ei, long long E,
                                 const float* __restrict__ da) {
    __shared__ __align__(16) float da_s[128];
    if (threadIdx.x < 128) da_s[threadIdx.x] = da[threadIdx.x];
    __syncthreads();

    const int is64 = g_is64;
    long long idx = (long long)blockIdx.x * blockDim.x + threadIdx.x;
    if (idx >= E * 4) return;
    long long e = idx >> 2;
    int h = (int)(idx & 3);
    long long s = get_idx(ei, e, is64);
    long long d = get_idx(ei, E + e, is64);
    const float4* sp4 = (const float4*)(g_sp + s * NF + h * 32);
    const float4* dp4 = (const float4*)(g_dp + d * NF + h * 32);
    const float4* wa4 = (const float4*)(da_s + h * 32);
    float acc = 0.0f;
#pragma unroll
    for (int g = 0; g < 8; g++) {
        float4 a = sp4[g], b = dp4[g], w = wa4[g];
        float v;
        v = a.x + b.x; v = v >= 0.0f ? v : 0.2f * v; acc += w.x * v;
        v = a.y + b.y; v = v >= 0.0f ? v : 0.2f * v; acc += w.y * v;
        v = a.z + b.z; v = v >= 0.0f ? v : 0.2f * v; acc += w.z * v;
        v = a.w + b.w; v = v >= 0.0f ? v : 0.2f * v; acc += w.w * v;
    }
    float ea = __expf(acc);
    g_exp[idx] = ea;
    atomicAdd(&g_denom[d * 4 + h], ea);
}

// ---------------- kernel E: weighted aggregation (warp per edge) --------------
__global__ void edge_agg_kernel(const void* __restrict__ ei, long long E,
                                float* __restrict__ outf) {
    const int is64 = g_is64;
    int lane = threadIdx.x & 31;
    long long e = (long long)blockIdx.x * 8 + (threadIdx.x >> 5);
    if (e >= E) return;
    long long s = get_idx(ei, e, is64);
    long long d = get_idx(ei, E + e, is64);
    int h = lane >> 3;
    float alpha = g_exp[e * 4 + h] / (g_denom[d * 4 + h] + 1e-16f);
    float4 v = ((const float4*)(g_sp + s * NF))[lane];
    float* p = outf + d * NF + lane * 4;
    atomicAdd(p + 0, v.x * alpha);
    atomicAdd(p + 1, v.y * alpha);
    atomicAdd(p + 2, v.z * alpha);
    atomicAdd(p + 3, v.w * alpha);
}

// ---------------- kernel G: residual + bias + PReLU ---------------------------
__global__ void finalize_kernel(const float* __restrict__ x, const float* __restrict__ bias,
                                const float* __restrict__ pa, float* __restrict__ outf,
                                long long total) {
    long long i = (long long)blockIdx.x * blockDim.x + threadIdx.x;
    if (i >= total) return;
    float v = outf[i] + x[i] + bias[i & 127];
    float a = pa[0];
    outf[i] = v >= 0.0f ? v : a * v;
}

// ---------------- launch -------------------------------------------------------
extern "C" void kernel_launch(void* const* d_in, const int* in_sizes, int n_in,
                              void* d_out, int out_size) {
    const float* x    = (const float*)d_in[0];
    const void*  ei   = d_in[1];
    const float* bw_s = (const float*)d_in[2];
    const float* sw_s = (const float*)d_in[3];
    const float* bw_d = (const float*)d_in[4];
    const float* sw_d = (const float*)d_in[5];
    const float* da   = (const float*)d_in[6];
    const float* bias = (const float*)d_in[7];
    const float* pa   = (const float*)d_in[8];
    float* outf = (float*)d_out;

    int       N = in_sizes[0] / NF;
    long long E = (long long)in_sizes[1] / 2;
    long long total = (long long)N * NF;

    cudaFuncSetAttribute(proj_gemm_kernel, cudaFuncAttributeMaxDynamicSharedMemorySize, SMEM_BYTES);

    detect_kernel<<<1, 32>>>((const int*)ei, E);
    zero_kernel<<<(int)((total + 255) / 256), 256>>>(outf, total, (long long)N * 4);
    prep_wt_kernel<<<(NIT * 2 * 256 * BPITCH + 255) / 256, 256>>>(bw_s, sw_s, bw_d, sw_d);
    proj_gemm_kernel<<<(N + TILE_M - 1) / TILE_M, 256, SMEM_BYTES>>>(x, N);
    edge_attn_kernel<<<(int)((E * 4 + 255) / 256), 256>>>(ei, E, da);
    edge_agg_kernel<<<(int)((E + 7) / 8), 256>>>(ei, E, outf);
    finalize_kernel<<<(int)((total + 255) / 256), 256>>>(x, bias, pa, outf, total);
}